// round 2
// baseline (speedup 1.0000x reference)
#include <cuda_runtime.h>

// GCN per-sample: out = relu(D^-1/2 (A+I) D^-1/2 (h0 W)) summed over nodes, dot fc_w, + fc_b
// B = 1e6, V = 9, F_IN = 5, F_HID = 3.  Pure HBM-streaming problem (~512 MB).

#define V      9
#define FIN    5
#define FH     3
#define TPB    96          // samples per block == threads per block
#define A_PER  (V*V)       // 81 floats per sample
#define H_PER  (V*FIN)     // 45 floats per sample

__global__ __launch_bounds__(TPB) void gcn_kernel(
    const float* __restrict__ gA,
    const float* __restrict__ gH,
    const float* __restrict__ gW,
    const float* __restrict__ gFw,
    const float* __restrict__ gFb,
    float* __restrict__ out,
    int B)
{
    __shared__ float sA[TPB * A_PER];   // 31,104 B
    __shared__ float sH[TPB * H_PER];   // 17,280 B  (total 48,384 B < 48 KB static limit)

    const int bstart = blockIdx.x * TPB;
    const int nS = min(TPB, B - bstart);

    // ---- Stage A: coalesced float4 copy (96*81 and 64*81 are both divisible by 4;
    //      block base offset 96*81*bid floats is 16B-aligned) ----
    {
        const int nFl = nS * A_PER;
        const int n4  = nFl >> 2;
        const float4* src = reinterpret_cast<const float4*>(gA + (size_t)bstart * A_PER);
        float4* dst = reinterpret_cast<float4*>(sA);
        for (int i = threadIdx.x; i < n4; i += TPB) dst[i] = src[i];
        for (int i = (n4 << 2) + threadIdx.x; i < nFl; i += TPB)
            sA[i] = gA[(size_t)bstart * A_PER + i];
    }
    // ---- Stage h0 ----
    {
        const int nFl = nS * H_PER;
        const int n4  = nFl >> 2;
        const float4* src = reinterpret_cast<const float4*>(gH + (size_t)bstart * H_PER);
        float4* dst = reinterpret_cast<float4*>(sH);
        for (int i = threadIdx.x; i < n4; i += TPB) dst[i] = src[i];
        for (int i = (n4 << 2) + threadIdx.x; i < nFl; i += TPB)
            sH[i] = gH[(size_t)bstart * H_PER + i];
    }
    __syncthreads();

    const int t = threadIdx.x;
    if (t >= nS) return;
    const float* a = sA + t * A_PER;   // per-thread stride 81: gcd(81 mod 32, 32)=1 -> conflict-free
    const float* h = sH + t * H_PER;   // stride 45: gcd(13,32)=1 -> conflict-free

    // deg_j = 1 (identity diag) + column-sum_j(A);  dinv_j = rsqrt(deg_j)
    float dinv[V];
    #pragma unroll
    for (int j = 0; j < V; j++) {
        float d = 1.0f;
        #pragma unroll
        for (int i = 0; i < V; i++) d += a[i * V + j];
        dinv[j] = rsqrtf(d);
    }

    // W is tiny & uniform across the warp -> broadcast loads
    float Wr[FIN][FH];
    #pragma unroll
    for (int f = 0; f < FIN; f++)
        #pragma unroll
        for (int c = 0; c < FH; c++)
            Wr[f][c] = __ldg(gW + f * FH + c);

    // t[j][c] = dinv_j * (h0 W)[j][c]
    float tj[V][FH];
    #pragma unroll
    for (int j = 0; j < V; j++) {
        #pragma unroll
        for (int c = 0; c < FH; c++) {
            float s = 0.0f;
            #pragma unroll
            for (int f = 0; f < FIN; f++)
                s = fmaf(h[j * FIN + f], Wr[f][c], s);
            tj[j][c] = dinv[j] * s;
        }
    }

    // h1[i][c] = relu(dinv_i * ( t[i][c]  +  sum_j A[i][j] * t[j][c] ))
    //   (the seeded t[i][c] is the +I diagonal contribution of AI = A + I)
    float acc0 = 0.f, acc1 = 0.f, acc2 = 0.f;
    #pragma unroll
    for (int i = 0; i < V; i++) {
        float s0 = tj[i][0], s1 = tj[i][1], s2 = tj[i][2];
        #pragma unroll
        for (int j = 0; j < V; j++) {
            float aij = a[i * V + j];
            s0 = fmaf(aij, tj[j][0], s0);
            s1 = fmaf(aij, tj[j][1], s1);
            s2 = fmaf(aij, tj[j][2], s2);
        }
        float di = dinv[i];
        acc0 += fmaxf(di * s0, 0.0f);
        acc1 += fmaxf(di * s1, 0.0f);
        acc2 += fmaxf(di * s2, 0.0f);
    }

    // pooled @ fc_w + fc_b
    float r = __ldg(gFb);
    r = fmaf(acc0, __ldg(gFw + 0), r);
    r = fmaf(acc1, __ldg(gFw + 1), r);
    r = fmaf(acc2, __ldg(gFw + 2), r);
    out[bstart + t] = r;
}

extern "C" void kernel_launch(void* const* d_in, const int* in_sizes, int n_in,
                              void* d_out, int out_size)
{
    const float* A   = (const float*)d_in[0];
    const float* h0  = (const float*)d_in[1];
    const float* W   = (const float*)d_in[2];
    const float* fcw = (const float*)d_in[3];
    const float* fcb = (const float*)d_in[4];
    float* out = (float*)d_out;

    const int B = in_sizes[0] / A_PER;   // 1,000,000
    const int grid = (B + TPB - 1) / TPB;
    gcn_kernel<<<grid, TPB>>>(A, h0, W, fcw, fcb, out, B);
}

// round 5
// speedup vs baseline: 1.5038x; 1.5038x over previous
#include <cuda_runtime.h>

// Batched tiny-GCN: out[b] = fc( sum_i relu( D^-1/2 (A+I) D^-1/2 (h0 W) )_i )
// B=1e6, V=9, F_IN=5, F_HID=3.  HBM-streaming: 512 MB total -> ~76us floor.
//
// R2 design: one WARP per block, tile = 32 samples staged into 16.1 KB smem
// with coalesced float4 loads. ~13 independent single-warp pipelines per SM
// at decorrelated phases -> DRAM stays busy while other warps compute.
// W / fc params live in __constant__ (zero register cost in FFMA).

#define V      9
#define FIN    5
#define FH     3
#define TPB    32
#define A_PER  (V*V)       // 81
#define H_PER  (V*FIN)     // 45
#define A_F4   ((TPB*A_PER)/4)   // 648 float4 per tile
#define H_F4   ((TPB*H_PER)/4)   // 360 float4 per tile

__constant__ float cW[FIN*FH];   // 15
__constant__ float cF[FH + 1];   // fc_w[3], fc_b

__global__ __launch_bounds__(TPB, 13) void gcn_kernel(
    const float* __restrict__ gA,
    const float* __restrict__ gH,
    float* __restrict__ out,
    int B)
{
    __shared__ float sA[TPB * A_PER];   // 10,368 B
    __shared__ float sH[TPB * H_PER];   //  5,760 B   (16,128 B total)

    const int lane   = threadIdx.x;
    const int bstart = blockIdx.x * TPB;
    const int nS     = min(TPB, B - bstart);

    if (nS == TPB) {
        // Fast path: full tile, fully-unrolled coalesced float4 staging.
        // Tile base byte offsets: 32*324*bid and 32*180*bid, both 16B-aligned.
        const float4* __restrict__ srcA = reinterpret_cast<const float4*>(gA + (size_t)bstart * A_PER);
        const float4* __restrict__ srcH = reinterpret_cast<const float4*>(gH + (size_t)bstart * H_PER);
        float4* dstA = reinterpret_cast<float4*>(sA);
        float4* dstH = reinterpret_cast<float4*>(sH);
        #pragma unroll
        for (int k = 0; k < A_F4 / TPB; k++)            // 20 iters
            dstA[lane + TPB * k] = srcA[lane + TPB * k];
        if (lane < A_F4 - TPB * (A_F4 / TPB))           // 8 tail
            dstA[lane + TPB * (A_F4 / TPB)] = srcA[lane + TPB * (A_F4 / TPB)];
        #pragma unroll
        for (int k = 0; k < H_F4 / TPB; k++)            // 11 iters
            dstH[lane + TPB * k] = srcH[lane + TPB * k];
        if (lane < H_F4 - TPB * (H_F4 / TPB))           // 8 tail
            dstH[lane + TPB * (H_F4 / TPB)] = srcH[lane + TPB * (H_F4 / TPB)];
    } else {
        // Ragged tail (not hit for B=1e6, kept for correctness)
        for (int i = lane; i < nS * A_PER; i += TPB) sA[i] = gA[(size_t)bstart * A_PER + i];
        for (int i = lane; i < nS * H_PER; i += TPB) sH[i] = gH[(size_t)bstart * H_PER + i];
    }
    __syncwarp();

    if (lane >= nS) return;
    const float* a = sA + lane * A_PER;   // stride 81: 81%32=17, coprime -> conflict-free
    const float* h = sH + lane * H_PER;   // stride 45: 45%32=13, coprime -> conflict-free

    // deg_j = 1 + colsum_j(A);  dinv_j = rsqrt(deg_j)
    float dinv[V];
    #pragma unroll
    for (int j = 0; j < V; j++) {
        float d = 1.0f;
        #pragma unroll
        for (int i = 0; i < V; i++) d += a[i * V + j];
        dinv[j] = rsqrtf(d);
    }

    // t[j][c] = dinv_j * (h0 W)[j][c]   (W from constant bank: no registers)
    float tj[V][FH];
    #pragma unroll
    for (int j = 0; j < V; j++) {
        #pragma unroll
        for (int c = 0; c < FH; c++) {
            float s = 0.0f;
            #pragma unroll
            for (int f = 0; f < FIN; f++)
                s = fmaf(h[j * FIN + f], cW[f * FH + c], s);
            tj[j][c] = dinv[j] * s;
        }
    }

    // h1[i][c] = relu(dinv_i * (t[i][c] + sum_j A[i][j] t[j][c])), pooled over i
    float acc0 = 0.f, acc1 = 0.f, acc2 = 0.f;
    #pragma unroll
    for (int i = 0; i < V; i++) {
        float s0 = tj[i][0], s1 = tj[i][1], s2 = tj[i][2];
        #pragma unroll
        for (int j = 0; j < V; j++) {
            float aij = a[i * V + j];
            s0 = fmaf(aij, tj[j][0], s0);
            s1 = fmaf(aij, tj[j][1], s1);
            s2 = fmaf(aij, tj[j][2], s2);
        }
        float di = dinv[i];
        acc0 += fmaxf(di * s0, 0.0f);
        acc1 += fmaxf(di * s1, 0.0f);
        acc2 += fmaxf(di * s2, 0.0f);
    }

    out[bstart + lane] = fmaf(acc0, cF[0], fmaf(acc1, cF[1], fmaf(acc2, cF[2], cF[3])));
}

extern "C" void kernel_launch(void* const* d_in, const int* in_sizes, int n_in,
                              void* d_out, int out_size)
{
    const float* A   = (const float*)d_in[0];
    const float* h0  = (const float*)d_in[1];
    const float* W   = (const float*)d_in[2];
    const float* fcw = (const float*)d_in[3];
    const float* fcb = (const float*)d_in[4];
    float* out = (float*)d_out;

    // Params -> constant bank (device-to-device async copies: graph-capturable)
    cudaMemcpyToSymbolAsync(cW, W,   FIN * FH * sizeof(float), 0, cudaMemcpyDeviceToDevice, 0);
    cudaMemcpyToSymbolAsync(cF, fcw, FH * sizeof(float),       0, cudaMemcpyDeviceToDevice, 0);
    cudaMemcpyToSymbolAsync(cF, fcb, sizeof(float), FH * sizeof(float), cudaMemcpyDeviceToDevice, 0);

    const int B = in_sizes[0] / A_PER;   // 1,000,000
    const int grid = (B + TPB - 1) / TPB;
    gcn_kernel<<<grid, TPB>>>(A, h0, out, B);
}

// round 8
// speedup vs baseline: 1.6780x; 1.1158x over previous
#include <cuda_runtime.h>
#include <cstdint>

// Batched tiny-GCN, B=1e6, V=9, F_IN=5, F_HID=3. Pure HBM stream (~512 MB, ~72us floor).
// R5: 4 warps/block (one per SMSP), each warp = independent cp.async double-buffered
// pipeline over 16-sample tiles. 3 blocks/SM -> 12 warps, prefetch always in flight.

#define V       9
#define FIN     5
#define FH      3
#define TPB     128
#define NWARP   4
#define VS      16                 // samples per warp-tile
#define A_PER   (V*V)              // 81
#define H_PER   (V*FIN)            // 45
#define SA_F    (VS*A_PER)         // 1296 floats
#define SH_F    (VS*H_PER)         // 720 floats
#define STAGE_F (SA_F+SH_F)        // 2016 floats = 8064 B
#define A_F4    (SA_F/4)           // 324
#define H_F4    (SH_F/4)           // 180
#define SMEM_BYTES (NWARP*2*STAGE_F*4)   // 64512

__constant__ float cW[FIN*FH];
__constant__ float cF[FH+1];       // fc_w[0..2], fc_b

__device__ __forceinline__ void cp16(uint32_t dst, const void* src) {
    asm volatile("cp.async.cg.shared.global [%0], [%1], 16;" :: "r"(dst), "l"(src));
}

__device__ __forceinline__ float gcn_sample(const float* __restrict__ a,
                                            const float* __restrict__ h)
{
    // deg_j = 1 + colsum_j(A);  dinv = rsqrt
    float dinv[V];
    #pragma unroll
    for (int j = 0; j < V; j++) {
        float d = 1.0f;
        #pragma unroll
        for (int i = 0; i < V; i++) d += a[i*V + j];
        dinv[j] = rsqrtf(d);
    }
    // t[j][c] = dinv_j * (h0 W)[j][c]
    float tj[V][FH];
    #pragma unroll
    for (int j = 0; j < V; j++) {
        #pragma unroll
        for (int c = 0; c < FH; c++) {
            float s = 0.0f;
            #pragma unroll
            for (int f = 0; f < FIN; f++)
                s = fmaf(h[j*FIN + f], cW[f*FH + c], s);
            tj[j][c] = dinv[j] * s;
        }
    }
    // pooled relu(dinv_i*(t[i] + sum_j A[i][j] t[j]))
    float acc0 = 0.f, acc1 = 0.f, acc2 = 0.f;
    #pragma unroll
    for (int i = 0; i < V; i++) {
        float s0 = tj[i][0], s1 = tj[i][1], s2 = tj[i][2];
        #pragma unroll
        for (int j = 0; j < V; j++) {
            float aij = a[i*V + j];
            s0 = fmaf(aij, tj[j][0], s0);
            s1 = fmaf(aij, tj[j][1], s1);
            s2 = fmaf(aij, tj[j][2], s2);
        }
        float di = dinv[i];
        acc0 += fmaxf(di*s0, 0.0f);
        acc1 += fmaxf(di*s1, 0.0f);
        acc2 += fmaxf(di*s2, 0.0f);
    }
    return fmaf(acc0, cF[0], fmaf(acc1, cF[1], fmaf(acc2, cF[2], cF[3])));
}

__global__ __launch_bounds__(TPB, 3) void gcn_kernel(
    const float* __restrict__ gA,
    const float* __restrict__ gH,
    float* __restrict__ out,
    int B)
{
    extern __shared__ float smem[];           // [NWARP][2][STAGE_F]
    const int wid  = threadIdx.x >> 5;
    const int lane = threadIdx.x & 31;
    float* buf[2] = { smem + (wid*2+0)*STAGE_F, smem + (wid*2+1)*STAGE_F };

    const int gw    = blockIdx.x * NWARP + wid;   // global warp id
    const int nw    = gridDim.x * NWARP;          // total warps
    const int nfull = B / VS;                     // full tiles (62500)

    // ---- prefetch helper: 16 cp.async per lane, fully coalesced float4 stream
    auto prefetch = [&](int tile, float* b) {
        const float4* __restrict__ srcA =
            reinterpret_cast<const float4*>(gA + (size_t)tile * SA_F);
        const float4* __restrict__ srcH =
            reinterpret_cast<const float4*>(gH + (size_t)tile * SH_F);
        uint32_t dA = (uint32_t)__cvta_generic_to_shared(b);
        uint32_t dH = dA + SA_F * 4;
        #pragma unroll
        for (int k = 0; k < A_F4/32; k++)                       // 10
            cp16(dA + (lane + 32*k)*16, srcA + lane + 32*k);
        if (lane < A_F4 - 32*(A_F4/32))                         // 4 tail
            cp16(dA + (32*(A_F4/32) + lane)*16, srcA + 32*(A_F4/32) + lane);
        #pragma unroll
        for (int k = 0; k < H_F4/32; k++)                       // 5
            cp16(dH + (lane + 32*k)*16, srcH + lane + 32*k);
        if (lane < H_F4 - 32*(H_F4/32))                         // 20 tail
            cp16(dH + (32*(H_F4/32) + lane)*16, srcH + 32*(H_F4/32) + lane);
    };

    // ---- warp-local double-buffered pipeline over strided tiles
    int t = gw;
    if (t < nfull) prefetch(t, buf[0]);
    asm volatile("cp.async.commit_group;");
    int s = 0;
    while (t < nfull) {
        const int t2 = t + nw;
        if (t2 < nfull) prefetch(t2, buf[s ^ 1]);
        asm volatile("cp.async.commit_group;");
        asm volatile("cp.async.wait_group 1;");
        __syncwarp();
        if (lane < VS) {
            const float* a = buf[s] + lane * A_PER;        // stride 81 -> conflict-free
            const float* h = buf[s] + SA_F + lane * H_PER; // stride 45 -> conflict-free
            out[(size_t)t * VS + lane] = gcn_sample(a, h);
        }
        __syncwarp();      // protect buf[s] before it is refilled next iteration
        s ^= 1;
        t = t2;
    }

    // ---- ragged remainder (B % 16 == 0 here; kept for generality)
    const int rem = B - nfull * VS;
    if (rem && blockIdx.x == 0 && wid == 0 && lane < rem) {
        const float* a = gA + (size_t)(nfull*VS + lane) * A_PER;
        const float* h = gH + (size_t)(nfull*VS + lane) * H_PER;
        out[nfull*VS + lane] = gcn_sample(a, h);
    }
}

extern "C" void kernel_launch(void* const* d_in, const int* in_sizes, int n_in,
                              void* d_out, int out_size)
{
    const float* A   = (const float*)d_in[0];
    const float* h0  = (const float*)d_in[1];
    const float* W   = (const float*)d_in[2];
    const float* fcw = (const float*)d_in[3];
    const float* fcb = (const float*)d_in[4];
    float* out = (float*)d_out;

    cudaMemcpyToSymbolAsync(cW, W,   FIN*FH*sizeof(float), 0, cudaMemcpyDeviceToDevice, 0);
    cudaMemcpyToSymbolAsync(cF, fcw, FH*sizeof(float),     0, cudaMemcpyDeviceToDevice, 0);
    cudaMemcpyToSymbolAsync(cF, fcb, sizeof(float), FH*sizeof(float), cudaMemcpyDeviceToDevice, 0);

    cudaFuncSetAttribute(gcn_kernel, cudaFuncAttributeMaxDynamicSharedMemorySize, SMEM_BYTES);

    const int B = in_sizes[0] / A_PER;     // 1,000,000
    const int grid = 148 * 3;              // 3 resident blocks/SM, grid-strided tiles
    gcn_kernel<<<grid, TPB, SMEM_BYTES>>>(A, h0, out, B);
}

// round 9
// speedup vs baseline: 1.8000x; 1.0727x over previous
#include <cuda_runtime.h>
#include <cstdint>

// Batched tiny-GCN, B=1e6, V=9, F_IN=5, F_HID=3. Pure HBM stream (~512 MB, ~72-76us floor).
// R8: bulk-async (TMA) staging + mbarrier, 100-sample block-tiles (25 samples/warp,
// all 4 SMSPs covered), double-buffered, 2 blocks/SM. Staging costs ~3 issued
// instructions per tile instead of ~16 LDGSTS; all lanes compute.

#define V       9
#define FIN     5
#define FH      3
#define TPB     128
#define SPB     100                      // samples per block-tile (1e6 / 100 = 10000 exact)
#define SPW     25                       // samples per warp
#define A_PER   (V*V)                    // 81
#define H_PER   (V*FIN)                  // 45
#define A_BYTES (SPB*A_PER*4)            // 32400
#define H_BYTES (SPB*H_PER*4)            // 18000
#define STAGE_BYTES (A_BYTES+H_BYTES)    // 50400
#define SMEM_BYTES  (2*STAGE_BYTES + 16) // + 2 mbarriers

__constant__ float cW[FIN*FH];
__constant__ float cF[FH+1];             // fc_w[0..2], fc_b

__device__ __forceinline__ void mbar_init(uint32_t mbar, uint32_t cnt) {
    asm volatile("mbarrier.init.shared.b64 [%0], %1;" :: "r"(mbar), "r"(cnt) : "memory");
}
__device__ __forceinline__ void mbar_expect_tx(uint32_t mbar, uint32_t tx) {
    asm volatile("mbarrier.arrive.expect_tx.shared.b64 _, [%0], %1;" :: "r"(mbar), "r"(tx) : "memory");
}
__device__ __forceinline__ void mbar_wait(uint32_t mbar, uint32_t phase) {
    asm volatile(
        "{\n\t.reg .pred P;\n\t"
        "W_%=:\n\t"
        "mbarrier.try_wait.parity.acquire.cta.shared::cta.b64 P, [%0], %1, 0x989680;\n\t"
        "@!P bra W_%=;\n\t}"
        :: "r"(mbar), "r"(phase) : "memory");
}
__device__ __forceinline__ void bulk_g2s(uint32_t dst, const void* src, uint32_t bytes, uint32_t mbar) {
    asm volatile("cp.async.bulk.shared::cta.global.mbarrier::complete_tx::bytes [%0], [%1], %2, [%3];"
                 :: "r"(dst), "l"(src), "r"(bytes), "r"(mbar) : "memory");
}

__device__ __forceinline__ float gcn_sample(const float* __restrict__ a,
                                            const float* __restrict__ h)
{
    // deg_j = 1 + colsum_j(A); dinv = rsqrt
    float dinv[V];
    #pragma unroll
    for (int j = 0; j < V; j++) {
        float d = 1.0f;
        #pragma unroll
        for (int i = 0; i < V; i++) d += a[i*V + j];
        dinv[j] = rsqrtf(d);
    }
    // t[j][c] = dinv_j * (h0 W)[j][c]
    float tj[V][FH];
    #pragma unroll
    for (int j = 0; j < V; j++) {
        #pragma unroll
        for (int c = 0; c < FH; c++) {
            float s = 0.0f;
            #pragma unroll
            for (int f = 0; f < FIN; f++)
                s = fmaf(h[j*FIN + f], cW[f*FH + c], s);
            tj[j][c] = dinv[j] * s;
        }
    }
    // pooled relu(dinv_i * (t[i] + sum_j A[i][j] t[j]))
    float acc0 = 0.f, acc1 = 0.f, acc2 = 0.f;
    #pragma unroll
    for (int i = 0; i < V; i++) {
        float s0 = tj[i][0], s1 = tj[i][1], s2 = tj[i][2];
        #pragma unroll
        for (int j = 0; j < V; j++) {
            float aij = a[i*V + j];
            s0 = fmaf(aij, tj[j][0], s0);
            s1 = fmaf(aij, tj[j][1], s1);
            s2 = fmaf(aij, tj[j][2], s2);
        }
        float di = dinv[i];
        acc0 += fmaxf(di*s0, 0.0f);
        acc1 += fmaxf(di*s1, 0.0f);
        acc2 += fmaxf(di*s2, 0.0f);
    }
    return fmaf(acc0, cF[0], fmaf(acc1, cF[1], fmaf(acc2, cF[2], cF[3])));
}

__global__ __launch_bounds__(TPB, 2) void gcn_kernel(
    const float* __restrict__ gA,
    const float* __restrict__ gH,
    float* __restrict__ out,
    int B)
{
    extern __shared__ __align__(16) unsigned char smem[];
    // layout: stage0 [A|H], stage1 [A|H], 2 mbarriers
    float* bufA0 = reinterpret_cast<float*>(smem);
    float* bufA1 = reinterpret_cast<float*>(smem + STAGE_BYTES);
    const uint32_t smemBase = (uint32_t)__cvta_generic_to_shared(smem);
    const uint32_t barBase  = smemBase + 2*STAGE_BYTES;

    const int tid  = threadIdx.x;
    const int wid  = tid >> 5;
    const int lane = tid & 31;

    if (tid == 0) { mbar_init(barBase, 1); mbar_init(barBase + 8, 1); }
    __syncthreads();

    const int nt     = B / SPB;
    const int stride = gridDim.x;
    int t = blockIdx.x;

    // first prefetch into stage 0
    if (tid == 0 && t < nt) {
        mbar_expect_tx(barBase, STAGE_BYTES);
        bulk_g2s(smemBase,           gA + (size_t)t * (SPB*A_PER), A_BYTES, barBase);
        bulk_g2s(smemBase + A_BYTES, gH + (size_t)t * (SPB*H_PER), H_BYTES, barBase);
    }

    uint32_t ph0 = 0, ph1 = 0;
    int s = 0;
    while (t < nt) {
        const int t2 = t + stride;
        // all warps finished reading buf[s^1] (previous iteration) before refill
        __syncthreads();
        if (tid == 0 && t2 < nt) {
            const uint32_t dst = smemBase + (s ^ 1) * STAGE_BYTES;
            const uint32_t bar = barBase + (s ^ 1) * 8;
            mbar_expect_tx(bar, STAGE_BYTES);
            bulk_g2s(dst,           gA + (size_t)t2 * (SPB*A_PER), A_BYTES, bar);
            bulk_g2s(dst + A_BYTES, gH + (size_t)t2 * (SPB*H_PER), H_BYTES, bar);
        }
        // wait for stage s data
        mbar_wait(barBase + s * 8, s ? ph1 : ph0);
        if (s) ph1 ^= 1; else ph0 ^= 1;

        if (lane < SPW) {
            const int sIdx = wid * SPW + lane;                 // 0..99
            const float* base = (s ? bufA1 : bufA0);
            const float* a = base + sIdx * A_PER;              // stride 81 (odd) -> conflict-free
            const float* h = base + SPB*A_PER + sIdx * H_PER;  // stride 45 (odd) -> conflict-free
            out[(size_t)t * SPB + sIdx] = gcn_sample(a, h);
        }
        s ^= 1;
        t = t2;
    }

    // ragged tail (B % 100 == 0 here; kept for generality)
    const int base = nt * SPB;
    const int rem  = B - base;
    if (rem && blockIdx.x == 0) {
        for (int i = tid; i < rem; i += TPB)
            out[base + i] = gcn_sample(gA + (size_t)(base+i) * A_PER,
                                       gH + (size_t)(base+i) * H_PER);
    }
}

extern "C" void kernel_launch(void* const* d_in, const int* in_sizes, int n_in,
                              void* d_out, int out_size)
{
    const float* A   = (const float*)d_in[0];
    const float* h0  = (const float*)d_in[1];
    const float* W   = (const float*)d_in[2];
    const float* fcw = (const float*)d_in[3];
    const float* fcb = (const float*)d_in[4];
    float* out = (float*)d_out;

    cudaMemcpyToSymbolAsync(cW, W,   FIN*FH*sizeof(float), 0, cudaMemcpyDeviceToDevice, 0);
    cudaMemcpyToSymbolAsync(cF, fcw, FH*sizeof(float),     0, cudaMemcpyDeviceToDevice, 0);
    cudaMemcpyToSymbolAsync(cF, fcb, sizeof(float), FH*sizeof(float), cudaMemcpyDeviceToDevice, 0);

    cudaFuncSetAttribute(gcn_kernel, cudaFuncAttributeMaxDynamicSharedMemorySize, SMEM_BYTES);

    const int B = in_sizes[0] / A_PER;    // 1,000,000
    const int grid = 148 * 2;             // 2 resident blocks/SM, grid-strided block-tiles
    gcn_kernel<<<grid, TPB, SMEM_BYTES>>>(A, h0, out, B);
}

// round 11
// speedup vs baseline: 1.8447x; 1.0248x over previous
#include <cuda_runtime.h>
#include <cstdint>

// Batched tiny-GCN, B=1e6, V=9, F_IN=5, F_HID=3. HBM stream (~512 MB).
// R9: warp-specialized producer (warp 4) + 3-stage ring of 128-sample tiles.
// Consumers: 4 warps, one sample per lane (all 128 lanes busy). No __syncthreads
// in steady state; producer runs up to 3 tiles ahead -> DRAM never idles.

#define V        9
#define FIN      5
#define FH       3
#define TPB      160                        // 4 compute warps + 1 producer warp
#define SPB      128                        // samples per stage (= compute lanes)
#define NSTAGE   3
#define A_PER    (V*V)                      // 81
#define H_PER    (V*FIN)                    // 45
#define A_BYTES  (SPB*A_PER*4)              // 41472
#define H_BYTES  (SPB*H_PER*4)              // 23040
#define STAGE_BYTES (A_BYTES+H_BYTES)       // 64512
#define BAR_BYTES   (NSTAGE*2*8)            // full[3], empty[3]
#define SMEM_BYTES  (NSTAGE*STAGE_BYTES + BAR_BYTES)   // 193584

__constant__ float cW[FIN*FH];
__constant__ float cF[FH+1];                // fc_w[0..2], fc_b

__device__ __forceinline__ void mbar_init(uint32_t mbar, uint32_t cnt) {
    asm volatile("mbarrier.init.shared.b64 [%0], %1;" :: "r"(mbar), "r"(cnt) : "memory");
}
__device__ __forceinline__ void mbar_expect_tx(uint32_t mbar, uint32_t tx) {
    asm volatile("mbarrier.arrive.expect_tx.shared.b64 _, [%0], %1;" :: "r"(mbar), "r"(tx) : "memory");
}
__device__ __forceinline__ void mbar_arrive(uint32_t mbar) {
    asm volatile("mbarrier.arrive.shared.b64 _, [%0];" :: "r"(mbar) : "memory");
}
__device__ __forceinline__ void mbar_wait(uint32_t mbar, uint32_t phase) {
    asm volatile(
        "{\n\t.reg .pred P;\n\t"
        "W_%=:\n\t"
        "mbarrier.try_wait.parity.acquire.cta.shared::cta.b64 P, [%0], %1, 0x989680;\n\t"
        "@!P bra W_%=;\n\t}"
        :: "r"(mbar), "r"(phase) : "memory");
}
__device__ __forceinline__ void mbar_wait_relaxed(uint32_t mbar, uint32_t phase) {
    asm volatile(
        "{\n\t.reg .pred P;\n\t"
        "W_%=:\n\t"
        "mbarrier.try_wait.parity.relaxed.cta.shared::cta.b64 P, [%0], %1, 0x989680;\n\t"
        "@!P bra W_%=;\n\t}"
        :: "r"(mbar), "r"(phase) : "memory");
}
__device__ __forceinline__ void bulk_g2s(uint32_t dst, const void* src, uint32_t bytes, uint32_t mbar) {
    asm volatile("cp.async.bulk.shared::cta.global.mbarrier::complete_tx::bytes [%0], [%1], %2, [%3];"
                 :: "r"(dst), "l"(src), "r"(bytes), "r"(mbar) : "memory");
}

__device__ __forceinline__ float gcn_sample(const float* __restrict__ a,
                                            const float* __restrict__ h)
{
    float dinv[V];
    #pragma unroll
    for (int j = 0; j < V; j++) {
        float d = 1.0f;
        #pragma unroll
        for (int i = 0; i < V; i++) d += a[i*V + j];
        dinv[j] = rsqrtf(d);
    }
    float tj[V][FH];
    #pragma unroll
    for (int j = 0; j < V; j++) {
        #pragma unroll
        for (int c = 0; c < FH; c++) {
            float s = 0.0f;
            #pragma unroll
            for (int f = 0; f < FIN; f++)
                s = fmaf(h[j*FIN + f], cW[f*FH + c], s);
            tj[j][c] = dinv[j] * s;
        }
    }
    float acc0 = 0.f, acc1 = 0.f, acc2 = 0.f;
    #pragma unroll
    for (int i = 0; i < V; i++) {
        float s0 = tj[i][0], s1 = tj[i][1], s2 = tj[i][2];
        #pragma unroll
        for (int j = 0; j < V; j++) {
            float aij = a[i*V + j];
            s0 = fmaf(aij, tj[j][0], s0);
            s1 = fmaf(aij, tj[j][1], s1);
            s2 = fmaf(aij, tj[j][2], s2);
        }
        float di = dinv[i];
        acc0 += fmaxf(di*s0, 0.0f);
        acc1 += fmaxf(di*s1, 0.0f);
        acc2 += fmaxf(di*s2, 0.0f);
    }
    return fmaf(acc0, cF[0], fmaf(acc1, cF[1], fmaf(acc2, cF[2], cF[3])));
}

__global__ __launch_bounds__(TPB, 1) void gcn_kernel(
    const float* __restrict__ gA,
    const float* __restrict__ gH,
    float* __restrict__ out,
    int B)
{
    extern __shared__ __align__(16) unsigned char smem[];
    const uint32_t smemBase = (uint32_t)__cvta_generic_to_shared(smem);
    const uint32_t barBase  = smemBase + NSTAGE * STAGE_BYTES;
    // barriers: full[s] at barBase + s*16, empty[s] at barBase + s*16 + 8

    const int tid = threadIdx.x;
    const int wid = tid >> 5;

    if (tid == 0) {
        #pragma unroll
        for (int s = 0; s < NSTAGE; s++) {
            mbar_init(barBase + s*16,     1);    // full: producer's expect_tx arrival
            mbar_init(barBase + s*16 + 8, SPB);  // empty: 128 consumer arrivals
        }
    }
    __syncthreads();

    const int nt     = B / SPB;          // 7812 full tiles
    const int stride = gridDim.x;

    if (wid == 4) {
        // ---------------- producer warp (lane 0 only) ----------------
        if ((tid & 31) == 0) {
            int s = 0; uint32_t ph = 1;  // producer phase starts 1: first empty-wait passes
            for (int t = blockIdx.x; t < nt; t += stride) {
                mbar_wait_relaxed(barBase + s*16 + 8, ph);   // stage s free?
                mbar_expect_tx(barBase + s*16, STAGE_BYTES);
                const uint32_t dst = smemBase + s * STAGE_BYTES;
                bulk_g2s(dst,           gA + (size_t)t * (SPB*A_PER), A_BYTES, barBase + s*16);
                bulk_g2s(dst + A_BYTES, gH + (size_t)t * (SPB*H_PER), H_BYTES, barBase + s*16);
                if (++s == NSTAGE) { s = 0; ph ^= 1; }
            }
        }
    } else {
        // ---------------- consumer warps: one sample per lane ----------------
        int s = 0; uint32_t ph = 0;
        for (int t = blockIdx.x; t < nt; t += stride) {
            mbar_wait(barBase + s*16, ph);                   // stage s full?
            const float* base = reinterpret_cast<const float*>(smem + s * STAGE_BYTES);
            const float* a = base + tid * A_PER;             // stride 81 (odd) -> conflict-free
            const float* h = base + SPB*A_PER + tid * H_PER; // stride 45 (odd) -> conflict-free
            out[(size_t)t * SPB + tid] = gcn_sample(a, h);
            mbar_arrive(barBase + s*16 + 8);                 // release: done with stage s
            if (++s == NSTAGE) { s = 0; ph ^= 1; }
        }
    }

    // ---------------- ragged tail (64 samples), straight from GMEM ----------------
    const int basei = nt * SPB;
    const int rem   = B - basei;
    if (rem && blockIdx.x == 0 && tid < rem) {
        out[basei + tid] = gcn_sample(gA + (size_t)(basei + tid) * A_PER,
                                      gH + (size_t)(basei + tid) * H_PER);
    }
}

extern "C" void kernel_launch(void* const* d_in, const int* in_sizes, int n_in,
                              void* d_out, int out_size)
{
    const float* A   = (const float*)d_in[0];
    const float* h0  = (const float*)d_in[1];
    const float* W   = (const float*)d_in[2];
    const float* fcw = (const float*)d_in[3];
    const float* fcb = (const float*)d_in[4];
    float* out = (float*)d_out;

    cudaMemcpyToSymbolAsync(cW, W,   FIN*FH*sizeof(float), 0, cudaMemcpyDeviceToDevice, 0);
    cudaMemcpyToSymbolAsync(cF, fcw, FH*sizeof(float),     0, cudaMemcpyDeviceToDevice, 0);
    cudaMemcpyToSymbolAsync(cF, fcb, sizeof(float), FH*sizeof(float), cudaMemcpyDeviceToDevice, 0);

    cudaFuncSetAttribute(gcn_kernel, cudaFuncAttributeMaxDynamicSharedMemorySize, SMEM_BYTES);

    const int B = in_sizes[0] / A_PER;    // 1,000,000
    const int grid = 148;                 // 1 block/SM (smem-bound), grid-strided tiles
    gcn_kernel<<<grid, TPB, SMEM_BYTES>>>(A, h0, out, B);
}

// round 12
// speedup vs baseline: 1.8768x; 1.0174x over previous
#include <cuda_runtime.h>
#include <cstdint>

// Batched tiny-GCN, B=1e6, V=9, F_IN=5, F_HID=3. HBM stream (~508 MB).
// R12: (1) no __constant__ setup copies (3 graph nodes removed; params via __ldg,
// hoisted); (2) deeper/finer ring: 4 stages x 96 samples, producer warp + 3
// consumer warps. Producer runs up to 4 tiles ahead; finer stage granularity.

#define V        9
#define FIN      5
#define FH       3
#define TPB      128                        // warps 0-2: consumers (96 lanes), warp 3: producer
#define SPB      96                         // samples per stage
#define NSTAGE   4
#define A_PER    (V*V)                      // 81
#define H_PER    (V*FIN)                    // 45
#define A_BYTES  (SPB*A_PER*4)              // 31104
#define H_BYTES  (SPB*H_PER*4)              // 17280
#define STAGE_BYTES (A_BYTES+H_BYTES)       // 48384
#define BAR_BYTES   (NSTAGE*16)
#define SMEM_BYTES  (NSTAGE*STAGE_BYTES + BAR_BYTES)   // 193600

__device__ __forceinline__ void mbar_init(uint32_t mbar, uint32_t cnt) {
    asm volatile("mbarrier.init.shared.b64 [%0], %1;" :: "r"(mbar), "r"(cnt) : "memory");
}
__device__ __forceinline__ void mbar_expect_tx(uint32_t mbar, uint32_t tx) {
    asm volatile("mbarrier.arrive.expect_tx.shared.b64 _, [%0], %1;" :: "r"(mbar), "r"(tx) : "memory");
}
__device__ __forceinline__ void mbar_arrive(uint32_t mbar) {
    asm volatile("mbarrier.arrive.shared.b64 _, [%0];" :: "r"(mbar) : "memory");
}
__device__ __forceinline__ void mbar_wait(uint32_t mbar, uint32_t phase) {
    asm volatile(
        "{\n\t.reg .pred P;\n\t"
        "W_%=:\n\t"
        "mbarrier.try_wait.parity.acquire.cta.shared::cta.b64 P, [%0], %1, 0x989680;\n\t"
        "@!P bra W_%=;\n\t}"
        :: "r"(mbar), "r"(phase) : "memory");
}
__device__ __forceinline__ void mbar_wait_relaxed(uint32_t mbar, uint32_t phase) {
    asm volatile(
        "{\n\t.reg .pred P;\n\t"
        "W_%=:\n\t"
        "mbarrier.try_wait.parity.relaxed.cta.shared::cta.b64 P, [%0], %1, 0x989680;\n\t"
        "@!P bra W_%=;\n\t}"
        :: "r"(mbar), "r"(phase) : "memory");
}
__device__ __forceinline__ void bulk_g2s(uint32_t dst, const void* src, uint32_t bytes, uint32_t mbar) {
    asm volatile("cp.async.bulk.shared::cta.global.mbarrier::complete_tx::bytes [%0], [%1], %2, [%3];"
                 :: "r"(dst), "l"(src), "r"(bytes), "r"(mbar) : "memory");
}

struct Params { float W[FIN][FH]; float fw0, fw1, fw2, fb; };

__device__ __forceinline__ Params load_params(const float* __restrict__ gW,
                                              const float* __restrict__ gFw,
                                              const float* __restrict__ gFb)
{
    Params p;
    #pragma unroll
    for (int f = 0; f < FIN; f++)
        #pragma unroll
        for (int c = 0; c < FH; c++)
            p.W[f][c] = __ldg(gW + f*FH + c);
    p.fw0 = __ldg(gFw + 0); p.fw1 = __ldg(gFw + 1); p.fw2 = __ldg(gFw + 2);
    p.fb  = __ldg(gFb);
    return p;
}

__device__ __forceinline__ float gcn_sample(const float* __restrict__ a,
                                            const float* __restrict__ h,
                                            const Params& p)
{
    // deg_j = 1 + colsum_j(A); dinv = rsqrt
    float dinv[V];
    #pragma unroll
    for (int j = 0; j < V; j++) {
        float d = 1.0f;
        #pragma unroll
        for (int i = 0; i < V; i++) d += a[i*V + j];
        dinv[j] = rsqrtf(d);
    }
    // t[j][c] = dinv_j * (h0 W)[j][c]
    float tj[V][FH];
    #pragma unroll
    for (int j = 0; j < V; j++) {
        #pragma unroll
        for (int c = 0; c < FH; c++) {
            float s = 0.0f;
            #pragma unroll
            for (int f = 0; f < FIN; f++)
                s = fmaf(h[j*FIN + f], p.W[f][c], s);
            tj[j][c] = dinv[j] * s;
        }
    }
    // pooled relu(dinv_i * (t[i] + sum_j A[i][j] t[j]))
    float acc0 = 0.f, acc1 = 0.f, acc2 = 0.f;
    #pragma unroll
    for (int i = 0; i < V; i++) {
        float s0 = tj[i][0], s1 = tj[i][1], s2 = tj[i][2];
        #pragma unroll
        for (int j = 0; j < V; j++) {
            float aij = a[i*V + j];
            s0 = fmaf(aij, tj[j][0], s0);
            s1 = fmaf(aij, tj[j][1], s1);
            s2 = fmaf(aij, tj[j][2], s2);
        }
        float di = dinv[i];
        acc0 += fmaxf(di*s0, 0.0f);
        acc1 += fmaxf(di*s1, 0.0f);
        acc2 += fmaxf(di*s2, 0.0f);
    }
    return fmaf(acc0, p.fw0, fmaf(acc1, p.fw1, fmaf(acc2, p.fw2, p.fb)));
}

__global__ __launch_bounds__(TPB, 1) void gcn_kernel(
    const float* __restrict__ gA,
    const float* __restrict__ gH,
    const float* __restrict__ gW,
    const float* __restrict__ gFw,
    const float* __restrict__ gFb,
    float* __restrict__ out,
    int B)
{
    extern __shared__ __align__(16) unsigned char smem[];
    const uint32_t smemBase = (uint32_t)__cvta_generic_to_shared(smem);
    const uint32_t barBase  = smemBase + NSTAGE * STAGE_BYTES;
    // full[s] at barBase + s*16, empty[s] at barBase + s*16 + 8

    const int tid = threadIdx.x;
    const int wid = tid >> 5;

    if (tid == 0) {
        #pragma unroll
        for (int s = 0; s < NSTAGE; s++) {
            mbar_init(barBase + s*16,     1);    // full: producer expect_tx
            mbar_init(barBase + s*16 + 8, SPB);  // empty: 96 consumer arrivals
        }
    }
    __syncthreads();

    const int nt     = B / SPB;          // 10416 full tiles
    const int stride = gridDim.x;

    if (wid == 3) {
        // ---------------- producer warp (lane 0) ----------------
        if ((tid & 31) == 0) {
            int s = 0; uint32_t ph = 1;  // first empty-wait passes immediately
            for (int t = blockIdx.x; t < nt; t += stride) {
                mbar_wait_relaxed(barBase + s*16 + 8, ph);
                mbar_expect_tx(barBase + s*16, STAGE_BYTES);
                const uint32_t dst = smemBase + s * STAGE_BYTES;
                bulk_g2s(dst,           gA + (size_t)t * (SPB*A_PER), A_BYTES, barBase + s*16);
                bulk_g2s(dst + A_BYTES, gH + (size_t)t * (SPB*H_PER), H_BYTES, barBase + s*16);
                if (++s == NSTAGE) { s = 0; ph ^= 1; }
            }
        }
    } else {
        // ---------------- consumer warps 0-2: one sample per lane ----------------
        const Params p = load_params(gW, gFw, gFb);
        int s = 0; uint32_t ph = 0;
        for (int t = blockIdx.x; t < nt; t += stride) {
            mbar_wait(barBase + s*16, ph);
            const float* base = reinterpret_cast<const float*>(smem + s * STAGE_BYTES);
            const float* a = base + tid * A_PER;             // stride 81 (odd) -> conflict-free
            const float* h = base + SPB*A_PER + tid * H_PER; // stride 45 (odd) -> conflict-free
            out[(size_t)t * SPB + tid] = gcn_sample(a, h, p);
            mbar_arrive(barBase + s*16 + 8);
            if (++s == NSTAGE) { s = 0; ph ^= 1; }
        }
    }

    // ---------------- ragged tail (1e6 - 96*10416 = 64 samples) ----------------
    const int basei = nt * SPB;
    const int rem   = B - basei;
    if (rem && blockIdx.x == 0 && tid < rem) {
        const Params p = load_params(gW, gFw, gFb);
        out[basei + tid] = gcn_sample(gA + (size_t)(basei + tid) * A_PER,
                                      gH + (size_t)(basei + tid) * H_PER, p);
    }
}

extern "C" void kernel_launch(void* const* d_in, const int* in_sizes, int n_in,
                              void* d_out, int out_size)
{
    const float* A   = (const float*)d_in[0];
    const float* h0  = (const float*)d_in[1];
    const float* W   = (const float*)d_in[2];
    const float* fcw = (const float*)d_in[3];
    const float* fcb = (const float*)d_in[4];
    float* out = (float*)d_out;

    cudaFuncSetAttribute(gcn_kernel, cudaFuncAttributeMaxDynamicSharedMemorySize, SMEM_BYTES);

    const int B = in_sizes[0] / A_PER;    // 1,000,000
    const int grid = 148;                 // 1 block/SM, grid-strided tiles
    gcn_kernel<<<grid, TPB, SMEM_BYTES>>>(A, h0, W, fcw, fcb, out, B);
}

// round 14
// speedup vs baseline: 1.9161x; 1.0210x over previous
#include <cuda_runtime.h>
#include <cstdint>

// Batched tiny-GCN, B=1e6, V=9, F_IN=5, F_HID=3. HBM stream (~508 MB).
// R13: warp-specialized producer + 2-stage ring of 96-sample tiles, and
// TWO independent blocks per SM (grid=296) so each SM carries two decorrelated
// copy/compute pipelines. Depth-2 suffices since compute (~1.3us) < copy (~2.2us):
// the TMA queue never drains. Producer warp sits on SMSP3 (HW-sleep waits).

#define V        9
#define FIN      5
#define FH       3
#define TPB      128                        // warps 0-2: consumers (96 lanes), warp 3: producer
#define SPB      96                         // samples per stage
#define NSTAGE   2
#define A_PER    (V*V)                      // 81
#define H_PER    (V*FIN)                    // 45
#define A_BYTES  (SPB*A_PER*4)              // 31104
#define H_BYTES  (SPB*H_PER*4)              // 17280
#define STAGE_BYTES (A_BYTES+H_BYTES)       // 48384
#define BAR_BYTES   (NSTAGE*16)
#define SMEM_BYTES  (NSTAGE*STAGE_BYTES + BAR_BYTES)   // 96800  -> 2 blocks/SM

__device__ __forceinline__ void mbar_init(uint32_t mbar, uint32_t cnt) {
    asm volatile("mbarrier.init.shared.b64 [%0], %1;" :: "r"(mbar), "r"(cnt) : "memory");
}
__device__ __forceinline__ void mbar_expect_tx(uint32_t mbar, uint32_t tx) {
    asm volatile("mbarrier.arrive.expect_tx.shared.b64 _, [%0], %1;" :: "r"(mbar), "r"(tx) : "memory");
}
__device__ __forceinline__ void mbar_arrive(uint32_t mbar) {
    asm volatile("mbarrier.arrive.shared.b64 _, [%0];" :: "r"(mbar) : "memory");
}
__device__ __forceinline__ void mbar_wait(uint32_t mbar, uint32_t phase) {
    asm volatile(
        "{\n\t.reg .pred P;\n\t"
        "W_%=:\n\t"
        "mbarrier.try_wait.parity.acquire.cta.shared::cta.b64 P, [%0], %1, 0x989680;\n\t"
        "@!P bra W_%=;\n\t}"
        :: "r"(mbar), "r"(phase) : "memory");
}
__device__ __forceinline__ void mbar_wait_relaxed(uint32_t mbar, uint32_t phase) {
    asm volatile(
        "{\n\t.reg .pred P;\n\t"
        "W_%=:\n\t"
        "mbarrier.try_wait.parity.relaxed.cta.shared::cta.b64 P, [%0], %1, 0x989680;\n\t"
        "@!P bra W_%=;\n\t}"
        :: "r"(mbar), "r"(phase) : "memory");
}
__device__ __forceinline__ void bulk_g2s(uint32_t dst, const void* src, uint32_t bytes, uint32_t mbar) {
    asm volatile("cp.async.bulk.shared::cta.global.mbarrier::complete_tx::bytes [%0], [%1], %2, [%3];"
                 :: "r"(dst), "l"(src), "r"(bytes), "r"(mbar) : "memory");
}

struct Params { float W[FIN][FH]; float fw0, fw1, fw2, fb; };

__device__ __forceinline__ Params load_params(const float* __restrict__ gW,
                                              const float* __restrict__ gFw,
                                              const float* __restrict__ gFb)
{
    Params p;
    #pragma unroll
    for (int f = 0; f < FIN; f++)
        #pragma unroll
        for (int c = 0; c < FH; c++)
            p.W[f][c] = __ldg(gW + f*FH + c);
    p.fw0 = __ldg(gFw + 0); p.fw1 = __ldg(gFw + 1); p.fw2 = __ldg(gFw + 2);
    p.fb  = __ldg(gFb);
    return p;
}

__device__ __forceinline__ float gcn_sample(const float* __restrict__ a,
                                            const float* __restrict__ h,
                                            const Params& p)
{
    // deg_j = 1 + colsum_j(A); dinv = rsqrt
    float dinv[V];
    #pragma unroll
    for (int j = 0; j < V; j++) {
        float d = 1.0f;
        #pragma unroll
        for (int i = 0; i < V; i++) d += a[i*V + j];
        dinv[j] = rsqrtf(d);
    }
    // t[j][c] = dinv_j * (h0 W)[j][c]
    float tj[V][FH];
    #pragma unroll
    for (int j = 0; j < V; j++) {
        #pragma unroll
        for (int c = 0; c < FH; c++) {
            float s = 0.0f;
            #pragma unroll
            for (int f = 0; f < FIN; f++)
                s = fmaf(h[j*FIN + f], p.W[f][c], s);
            tj[j][c] = dinv[j] * s;
        }
    }
    // pooled relu(dinv_i * (t[i] + sum_j A[i][j] t[j]))
    float acc0 = 0.f, acc1 = 0.f, acc2 = 0.f;
    #pragma unroll
    for (int i = 0; i < V; i++) {
        float s0 = tj[i][0], s1 = tj[i][1], s2 = tj[i][2];
        #pragma unroll
        for (int j = 0; j < V; j++) {
            float aij = a[i*V + j];
            s0 = fmaf(aij, tj[j][0], s0);
            s1 = fmaf(aij, tj[j][1], s1);
            s2 = fmaf(aij, tj[j][2], s2);
        }
        float di = dinv[i];
        acc0 += fmaxf(di*s0, 0.0f);
        acc1 += fmaxf(di*s1, 0.0f);
        acc2 += fmaxf(di*s2, 0.0f);
    }
    return fmaf(acc0, p.fw0, fmaf(acc1, p.fw1, fmaf(acc2, p.fw2, p.fb)));
}

__global__ __launch_bounds__(TPB, 2) void gcn_kernel(
    const float* __restrict__ gA,
    const float* __restrict__ gH,
    const float* __restrict__ gW,
    const float* __restrict__ gFw,
    const float* __restrict__ gFb,
    float* __restrict__ out,
    int B)
{
    extern __shared__ __align__(16) unsigned char smem[];
    const uint32_t smemBase = (uint32_t)__cvta_generic_to_shared(smem);
    const uint32_t barBase  = smemBase + NSTAGE * STAGE_BYTES;
    // full[s] at barBase + s*16, empty[s] at barBase + s*16 + 8

    const int tid = threadIdx.x;
    const int wid = tid >> 5;

    if (tid == 0) {
        #pragma unroll
        for (int s = 0; s < NSTAGE; s++) {
            mbar_init(barBase + s*16,     1);    // full: producer expect_tx
            mbar_init(barBase + s*16 + 8, SPB);  // empty: 96 consumer arrivals
        }
    }
    __syncthreads();

    const int nt     = B / SPB;          // 10416 full tiles
    const int stride = gridDim.x;

    if (wid == 3) {
        // ---------------- producer warp (lane 0), SMSP 3 ----------------
        if ((tid & 31) == 0) {
            int s = 0; uint32_t ph = 1;  // first empty-wait passes immediately
            for (int t = blockIdx.x; t < nt; t += stride) {
                mbar_wait_relaxed(barBase + s*16 + 8, ph);
                mbar_expect_tx(barBase + s*16, STAGE_BYTES);
                const uint32_t dst = smemBase + s * STAGE_BYTES;
                bulk_g2s(dst,           gA + (size_t)t * (SPB*A_PER), A_BYTES, barBase + s*16);
                bulk_g2s(dst + A_BYTES, gH + (size_t)t * (SPB*H_PER), H_BYTES, barBase + s*16);
                if (++s == NSTAGE) { s = 0; ph ^= 1; }
            }
        }
    } else {
        // ---------------- consumer warps 0-2 (SMSP 0-2): one sample per lane ----------------
        const Params p = load_params(gW, gFw, gFb);
        int s = 0; uint32_t ph = 0;
        for (int t = blockIdx.x; t < nt; t += stride) {
            mbar_wait(barBase + s*16, ph);
            const float* base = reinterpret_cast<const float*>(smem + s * STAGE_BYTES);
            const float* a = base + tid * A_PER;             // stride 81 (odd) -> conflict-free
            const float* h = base + SPB*A_PER + tid * H_PER; // stride 45 (odd) -> conflict-free
            out[(size_t)t * SPB + tid] = gcn_sample(a, h, p);
            mbar_arrive(barBase + s*16 + 8);
            if (++s == NSTAGE) { s = 0; ph ^= 1; }
        }
    }

    // ---------------- ragged tail (1e6 - 96*10416 = 64 samples) ----------------
    const int basei = nt * SPB;
    const int rem   = B - basei;
    if (rem && blockIdx.x == 0 && tid < rem) {
        const Params p = load_params(gW, gFw, gFb);
        out[basei + tid] = gcn_sample(gA + (size_t)(basei + tid) * A_PER,
                                      gH + (size_t)(basei + tid) * H_PER, p);
    }
}

extern "C" void kernel_launch(void* const* d_in, const int* in_sizes, int n_in,
                              void* d_out, int out_size)
{
    const float* A   = (const float*)d_in[0];
    const float* h0  = (const float*)d_in[1];
    const float* W   = (const float*)d_in[2];
    const float* fcw = (const float*)d_in[3];
    const float* fcb = (const float*)d_in[4];
    float* out = (float*)d_out;

    cudaFuncSetAttribute(gcn_kernel, cudaFuncAttributeMaxDynamicSharedMemorySize, SMEM_BYTES);

    const int B = in_sizes[0] / A_PER;    // 1,000,000
    const int grid = 148 * 2;             // 2 blocks/SM, grid-strided tiles
    gcn_kernel<<<grid, TPB, SMEM_BYTES>>>(A, h0, W, fcw, fcb, out, B);
}